// round 11
// baseline (speedup 1.0000x reference)
#include <cuda_runtime.h>
#include <math.h>

// Problem constants (fixed by the dataset): C=256 channels.
#define CCH   256
#define WR    64      // rows per warp (even)
#define MAXB  8       // scenes
#define NPART 256     // partial-sum blocks for scene means

__device__ float g_part[NPART][MAXB * 3];
__device__ float g_mean[MAXB * 3];
__device__ int   g_offs[MAXB + 1];

// Resolve lengths dtype (int32 vs int64) and build prefix offsets, per-thread.
__device__ __forceinline__ void resolve_offs(const void* __restrict__ lraw,
                                             int n, int b, int* offs, float* len)
{
    const long long* l64 = (const long long*)lraw;
    const int*       l32 = (const int*)lraw;
    long long s64 = 0;
    for (int i = 0; i < b; i++) s64 += l64[i];
    bool is64 = (s64 == (long long)n);
    int o = 0;
    offs[0] = 0;
    for (int i = 0; i < MAXB; i++) {
        long long L = (i < b) ? (is64 ? l64[i] : (long long)l32[i]) : 0;
        o += (int)L;
        offs[i + 1] = (i < b) ? o : n;
        if (len) len[i] = (float)((L < 1) ? 1 : L);
    }
}

// ---------------------------------------------------------------------------
// Kernel 1: per-block partial sums of coords per scene. 4 rows/thread via
// three coalesced float4 loads (12 floats = 4 rows x 3 comps).
// ---------------------------------------------------------------------------
__global__ __launch_bounds__(256) void k_partial(
    const float* __restrict__ coord, const void* __restrict__ lraw, int n, int b)
{
    int offs[MAXB + 1];
    resolve_offs(lraw, n, b, offs, nullptr);

    float acc[MAXB][3];
#pragma unroll
    for (int s = 0; s < MAXB; s++) { acc[s][0] = 0.f; acc[s][1] = 0.f; acc[s][2] = 0.f; }

    int ngrp = (n + 3) >> 2;                       // groups of 4 rows
    int grp_per_block = (ngrp + gridDim.x - 1) / gridDim.x;
    int g0 = blockIdx.x * grp_per_block;
    int g1 = min(g0 + grp_per_block, ngrp);

    const float4* c4 = (const float4*)coord;
    for (int g = g0 + (int)threadIdx.x; g < g1; g += blockDim.x) {
        int r = g << 2;
        float v[12];
        if (r + 4 <= n) {
            float4 a = c4[3 * g + 0];
            float4 bq = c4[3 * g + 1];
            float4 c = c4[3 * g + 2];
            v[0]=a.x; v[1]=a.y; v[2]=a.z; v[3]=a.w;
            v[4]=bq.x; v[5]=bq.y; v[6]=bq.z; v[7]=bq.w;
            v[8]=c.x; v[9]=c.y; v[10]=c.z; v[11]=c.w;
        } else {
#pragma unroll
            for (int j = 0; j < 12; j++)
                v[j] = (r * 3 + j < n * 3) ? coord[r * 3 + j] : 0.f;
        }
#pragma unroll
        for (int k = 0; k < 4; k++) {
            int rr = r + k;
            if (rr < n) {
                int seg = 0;
#pragma unroll
                for (int s = 1; s < MAXB; s++) if (s < b && rr >= offs[s]) seg = s;
                acc[seg][0] += v[3 * k + 0];
                acc[seg][1] += v[3 * k + 1];
                acc[seg][2] += v[3 * k + 2];
            }
        }
    }

    __shared__ float sm[256][MAXB * 3];
#pragma unroll
    for (int s = 0; s < MAXB; s++) {
        sm[threadIdx.x][s * 3 + 0] = acc[s][0];
        sm[threadIdx.x][s * 3 + 1] = acc[s][1];
        sm[threadIdx.x][s * 3 + 2] = acc[s][2];
    }
    __syncthreads();
    if (threadIdx.x < MAXB * 3) {
        float s_ = 0.f;
        for (int t = 0; t < 256; t++) s_ += sm[t][threadIdx.x];
        g_part[blockIdx.x][threadIdx.x] = s_;
    }
}

// ---------------------------------------------------------------------------
// Kernel 2: finalize scene means + publish offsets (1 block, deterministic).
// ---------------------------------------------------------------------------
__global__ void k_final(const void* __restrict__ lraw, int n, int b)
{
    __shared__ int   offs[MAXB + 1];
    __shared__ float len[MAXB];
    if (threadIdx.x == 0) {
        int o_[MAXB + 1]; float l_[MAXB];
        resolve_offs(lraw, n, b, o_, l_);
        for (int i = 0; i <= MAXB; i++) offs[i] = o_[i];
        for (int i = 0; i < MAXB; i++)  len[i]  = l_[i];
    }
    __syncthreads();
    int k = threadIdx.x;
    if (k < b * 3) {
        float s_ = 0.f;
        for (int p = 0; p < NPART; p++) s_ += g_part[p][k];
        g_mean[k] = s_ / len[k / 3];
    }
    if (k <= MAXB) g_offs[k] = offs[k];
}

// ---------------------------------------------------------------------------
// Kernel 3: fused main kernel, pairwise row processing.
// 128-thread blocks (4 warps). One warp owns WR=64 contiguous rows; lane owns
// 8 channels: c = lane*4+j (j<4), c = 128+lane*4+(j-4) (j>=4).
// Params live in smem; each param set is loaded ONCE PER ROW PAIR (halves
// LDS crossbar traffic vs per-row loads). Rolling 4-row register window
// supplies the depthwise conv for the two emitted rows.
// ---------------------------------------------------------------------------
#define LD8(dst, p) { float4 _u = s_par[p][lane]; float4 _v = s_par[p][32 + lane]; \
    dst[0]=_u.x; dst[1]=_u.y; dst[2]=_u.z; dst[3]=_u.w; \
    dst[4]=_v.x; dst[5]=_v.y; dst[6]=_v.z; dst[7]=_v.w; }

__global__ __launch_bounds__(128) void k_main(
    const float* __restrict__ feat, const float* __restrict__ coord,
    const float* __restrict__ w_xyz, const float* __restrict__ b_xyz,
    const float* __restrict__ g1, const float* __restrict__ be1,
    const float* __restrict__ w_conv, const float* __restrict__ b_conv,
    const float* __restrict__ g2, const float* __restrict__ be2,
    float* __restrict__ out, int n, int b)
{
    __shared__ float4 s_par[12][64];     // 12 param arrays x 256 ch
    __shared__ int    s_offs[MAXB + 1];
    __shared__ float  s_mean[MAXB * 3];

    const int tid = threadIdx.x;
    for (int c = tid; c < CCH; c += 128) {
        ((float*)s_par[0])[c]  = w_xyz[c];
        ((float*)s_par[1])[c]  = w_xyz[CCH + c];
        ((float*)s_par[2])[c]  = w_xyz[2 * CCH + c];
        ((float*)s_par[3])[c]  = b_xyz[c];
        ((float*)s_par[4])[c]  = g1[c];
        ((float*)s_par[5])[c]  = be1[c];
        ((float*)s_par[6])[c]  = w_conv[3 * c + 0];
        ((float*)s_par[7])[c]  = w_conv[3 * c + 1];
        ((float*)s_par[8])[c]  = w_conv[3 * c + 2];
        ((float*)s_par[9])[c]  = b_conv[c];
        ((float*)s_par[10])[c] = g2[c];
        ((float*)s_par[11])[c] = be2[c];
    }
    if (tid <= MAXB)    s_offs[tid] = g_offs[tid];
    if (tid < MAXB * 3) s_mean[tid] = g_mean[tid];
    __syncthreads();

    const int lane  = tid & 31;
    const int gwarp = blockIdx.x * 4 + (tid >> 5);
    const int start = gwarp * WR;
    if (start >= n) return;
    const int end = min(start + WR, n);

    // Incremental segment state (rows visited in increasing order).
    int seg = 0;
    {
        int r0 = (start > 0) ? start - 1 : 0;
        while (seg < b - 1 && r0 >= s_offs[seg + 1]) seg++;
    }
    int bnd = s_offs[seg + 1];
    float mx = s_mean[seg * 3 + 0];
    float my = s_mean[seg * 3 + 1];
    float mz = s_mean[seg * 3 + 2];

    const float inv = 1.0f / (float)CCH;

    auto track = [&](int r) -> int {
        while (r >= bnd) {
            seg++;
            bnd = s_offs[seg + 1];
            mx = s_mean[seg * 3 + 0];
            my = s_mean[seg * 3 + 1];
            mz = s_mean[seg * 3 + 2];
        }
        return seg;
    };

    // Single-row pos-embed (prologue only).
    auto row_pos1 = [&](int r, float* f, float* ft) -> int {
        int sg = track(r);
        float cx = coord[3 * r + 0] - mx;
        float cy = coord[3 * r + 1] - my;
        float cz = coord[3 * r + 2] - mz;
        float wa[8], wb[8], wcx[8], wd[8];
        LD8(wa, 0); LD8(wb, 1); LD8(wcx, 2); LD8(wd, 3);
        float x[8], s1 = 0.f, s2 = 0.f;
#pragma unroll
        for (int j = 0; j < 8; j++) {
            float v = fmaf(cx, wa[j], fmaf(cy, wb[j], fmaf(cz, wcx[j], wd[j])));
            x[j] = v; s1 += v; s2 = fmaf(v, v, s2);
        }
#pragma unroll
        for (int o = 16; o > 0; o >>= 1) {
            s1 += __shfl_xor_sync(0xffffffffu, s1, o);
            s2 += __shfl_xor_sync(0xffffffffu, s2, o);
        }
        float mu = s1 * inv, var = fmaf(-mu, mu, s2 * inv);
        float rstd = rsqrtf(var + 1e-5f);
        const float4* fp4 = (const float4*)(feat + (long)r * CCH);
        float4 a = fp4[lane], q = fp4[32 + lane];
        ft[0]=a.x; ft[1]=a.y; ft[2]=a.z; ft[3]=a.w;
        ft[4]=q.x; ft[5]=q.y; ft[6]=q.z; ft[7]=q.w;
        LD8(wa, 4); LD8(wb, 5);
#pragma unroll
        for (int j = 0; j < 8; j++) {
            float t  = (x[j] - mu) * rstd;
            float ln = fmaf(t, wa[j], wb[j]);
            float ge = 0.5f * ln * (1.0f + erff(ln * 0.70710678118654752f));
            f[j] = ft[j] + ge;
        }
        return sg;
    };

    // Window state: rows r-1, r (outputs pending), and raw feat of row r.
    float fp[8], fc[8], ftc[8];
    int segp, segc;

    if (start > 0) {
        float d_[8];
        segp = row_pos1(start - 1, fp, d_);
    } else {
#pragma unroll
        for (int j = 0; j < 8; j++) fp[j] = 0.f;
        segp = -1;
    }
    segc = row_pos1(start, fc, ftc);

#pragma unroll 1
    for (int r = start; r < end; r += 2) {
        // ---- Phase 1: pos-embed for rows A=r+1, B=r+2 (shared param loads)
        int rA = r + 1, rB = r + 2;
        bool vA = (rA < n), vB = (rB < n);
        int segA = -2, segB = -2;
        float cxA=0,cyA=0,czA=0, cxB=0,cyB=0,czB=0;
        if (vA) {
            segA = track(rA);
            cxA = coord[3 * rA + 0] - mx;
            cyA = coord[3 * rA + 1] - my;
            czA = coord[3 * rA + 2] - mz;
        }
        if (vB) {
            segB = track(rB);
            cxB = coord[3 * rB + 0] - mx;
            cyB = coord[3 * rB + 1] - my;
            czB = coord[3 * rB + 2] - mz;
        }

        float f1[8], f2[8], ft1[8], ft2[8];
        {
            float wa[8], wb[8], wcx[8], wd[8];
            LD8(wa, 0); LD8(wb, 1); LD8(wcx, 2); LD8(wd, 3);

            float xA[8], xB[8];
            float s1a = 0.f, s2a = 0.f, s1b = 0.f, s2b = 0.f;
#pragma unroll
            for (int j = 0; j < 8; j++) {
                float va = fmaf(cxA, wa[j], fmaf(cyA, wb[j], fmaf(czA, wcx[j], wd[j])));
                float vb = fmaf(cxB, wa[j], fmaf(cyB, wb[j], fmaf(czB, wcx[j], wd[j])));
                xA[j] = va; xB[j] = vb;
                s1a += va; s2a = fmaf(va, va, s2a);
                s1b += vb; s2b = fmaf(vb, vb, s2b);
            }
#pragma unroll
            for (int o = 16; o > 0; o >>= 1) {
                s1a += __shfl_xor_sync(0xffffffffu, s1a, o);
                s2a += __shfl_xor_sync(0xffffffffu, s2a, o);
                s1b += __shfl_xor_sync(0xffffffffu, s1b, o);
                s2b += __shfl_xor_sync(0xffffffffu, s2b, o);
            }
            float muA = s1a * inv, rstdA = rsqrtf(fmaf(-muA, muA, s2a * inv) + 1e-5f);
            float muB = s1b * inv, rstdB = rsqrtf(fmaf(-muB, muB, s2b * inv) + 1e-5f);

            if (vA) {
                const float4* fp4 = (const float4*)(feat + (long)rA * CCH);
                float4 a = fp4[lane], q = fp4[32 + lane];
                ft1[0]=a.x; ft1[1]=a.y; ft1[2]=a.z; ft1[3]=a.w;
                ft1[4]=q.x; ft1[5]=q.y; ft1[6]=q.z; ft1[7]=q.w;
            } else {
#pragma unroll
                for (int j = 0; j < 8; j++) ft1[j] = 0.f;
            }
            if (vB) {
                const float4* fp4 = (const float4*)(feat + (long)rB * CCH);
                float4 a = fp4[lane], q = fp4[32 + lane];
                ft2[0]=a.x; ft2[1]=a.y; ft2[2]=a.z; ft2[3]=a.w;
                ft2[4]=q.x; ft2[5]=q.y; ft2[6]=q.z; ft2[7]=q.w;
            } else {
#pragma unroll
                for (int j = 0; j < 8; j++) ft2[j] = 0.f;
            }

            LD8(wa, 4); LD8(wb, 5);   // g1, be1
#pragma unroll
            for (int j = 0; j < 8; j++) {
                float tA  = (xA[j] - muA) * rstdA;
                float lnA = fmaf(tA, wa[j], wb[j]);
                float geA = 0.5f * lnA * (1.0f + erff(lnA * 0.70710678118654752f));
                f1[j] = vA ? (ft1[j] + geA) : 0.f;
                float tB  = (xB[j] - muB) * rstdB;
                float lnB = fmaf(tB, wa[j], wb[j]);
                float geB = 0.5f * lnB * (1.0f + erff(lnB * 0.70710678118654752f));
                f2[j] = vB ? (ft2[j] + geB) : 0.f;
            }
        }

        // ---- Phase 2: conv + LN2 for rows r and r+1 (shared param loads)
        bool eA = (rA < end);        // emit row r+1?
        float m0p = (segp == segc) ? 1.f : 0.f;
        float m0n = (segA == segc) ? 1.f : 0.f;
        float m1p = (segc == segA) ? 1.f : 0.f;
        float m1n = (segB == segA) ? 1.f : 0.f;

        float wa[8], wb[8], wcx[8], wd[8];
        LD8(wa, 6); LD8(wb, 7); LD8(wcx, 8); LD8(wd, 9);

        float y0[8], y1[8];
        float s10 = 0.f, s20 = 0.f, s11 = 0.f, s21 = 0.f;
#pragma unroll
        for (int j = 0; j < 8; j++) {
            float cv0 = fmaf(fp[j] * m0p, wa[j],
                        fmaf(fc[j], wb[j],
                        fmaf(f1[j] * m0n, wcx[j], wd[j])));
            float v0 = ftc[j] + cv0;
            y0[j] = v0; s10 += v0; s20 = fmaf(v0, v0, s20);

            float cv1 = fmaf(fc[j] * m1p, wa[j],
                        fmaf(f1[j], wb[j],
                        fmaf(f2[j] * m1n, wcx[j], wd[j])));
            float v1 = ft1[j] + cv1;
            y1[j] = v1; s11 += v1; s21 = fmaf(v1, v1, s21);
        }
#pragma unroll
        for (int o = 16; o > 0; o >>= 1) {
            s10 += __shfl_xor_sync(0xffffffffu, s10, o);
            s20 += __shfl_xor_sync(0xffffffffu, s20, o);
            s11 += __shfl_xor_sync(0xffffffffu, s11, o);
            s21 += __shfl_xor_sync(0xffffffffu, s21, o);
        }
        float mu0 = s10 * inv, rstd0 = rsqrtf(fmaf(-mu0, mu0, s20 * inv) + 1e-5f);
        float mu1 = s11 * inv, rstd1 = rsqrtf(fmaf(-mu1, mu1, s21 * inv) + 1e-5f);

        LD8(wa, 10); LD8(wb, 11);  // g2, be2
        {
            float4 o1, o2;
            o1.x = fmaf((y0[0] - mu0) * rstd0, wa[0], wb[0]);
            o1.y = fmaf((y0[1] - mu0) * rstd0, wa[1], wb[1]);
            o1.z = fmaf((y0[2] - mu0) * rstd0, wa[2], wb[2]);
            o1.w = fmaf((y0[3] - mu0) * rstd0, wa[3], wb[3]);
            o2.x = fmaf((y0[4] - mu0) * rstd0, wa[4], wb[4]);
            o2.y = fmaf((y0[5] - mu0) * rstd0, wa[5], wb[5]);
            o2.z = fmaf((y0[6] - mu0) * rstd0, wa[6], wb[6]);
            o2.w = fmaf((y0[7] - mu0) * rstd0, wa[7], wb[7]);
            float4* op4 = (float4*)(out + (long)r * CCH);
            op4[lane]      = o1;
            op4[32 + lane] = o2;
        }
        if (eA) {
            float4 o1, o2;
            o1.x = fmaf((y1[0] - mu1) * rstd1, wa[0], wb[0]);
            o1.y = fmaf((y1[1] - mu1) * rstd1, wa[1], wb[1]);
            o1.z = fmaf((y1[2] - mu1) * rstd1, wa[2], wb[2]);
            o1.w = fmaf((y1[3] - mu1) * rstd1, wa[3], wb[3]);
            o2.x = fmaf((y1[4] - mu1) * rstd1, wa[4], wb[4]);
            o2.y = fmaf((y1[5] - mu1) * rstd1, wa[5], wb[5]);
            o2.z = fmaf((y1[6] - mu1) * rstd1, wa[6], wb[6]);
            o2.w = fmaf((y1[7] - mu1) * rstd1, wa[7], wb[7]);
            float4* op4 = (float4*)(out + (long)rA * CCH);
            op4[lane]      = o1;
            op4[32 + lane] = o2;
        }

        // rotate window by 2 rows
        segp = segA; segc = segB;
#pragma unroll
        for (int j = 0; j < 8; j++) {
            fp[j]  = f1[j];
            fc[j]  = f2[j];
            ftc[j] = ft2[j];
        }
    }
}

// ---------------------------------------------------------------------------
extern "C" void kernel_launch(void* const* d_in, const int* in_sizes, int n_in,
                              void* d_out, int out_size)
{
    const float* feat    = (const float*)d_in[0];
    const float* coord   = (const float*)d_in[1];
    const void*  lengths = (const void*)d_in[2];
    const float* w_xyz   = (const float*)d_in[3];
    const float* b_xyz   = (const float*)d_in[4];
    const float* g1      = (const float*)d_in[5];
    const float* be1     = (const float*)d_in[6];
    const float* w_conv  = (const float*)d_in[7];
    const float* b_conv  = (const float*)d_in[8];
    const float* g2      = (const float*)d_in[9];
    const float* be2     = (const float*)d_in[10];
    float*       out     = (float*)d_out;

    int n = in_sizes[0] / CCH;
    int b = in_sizes[2];
    if (b > MAXB) b = MAXB;

    k_partial<<<NPART, 256>>>(coord, lengths, n, b);
    k_final<<<1, 32>>>(lengths, n, b);

    int warps  = (n + WR - 1) / WR;
    int blocks = (warps + 3) / 4;
    k_main<<<blocks, 128>>>(feat, coord, w_xyz, b_xyz, g1, be1,
                            w_conv, b_conv, g2, be2, out, n, b);
}

// round 14
// speedup vs baseline: 1.0476x; 1.0476x over previous
#include <cuda_runtime.h>
#include <math.h>

// Problem constants (fixed by the dataset): C=256 channels.
#define CCH   256
#define WR    64      // rows per warp
#define MAXB  8       // scenes
#define NPART 256     // partial-sum blocks for scene means

__device__ float g_part[NPART][MAXB * 3];
__device__ float g_mean[MAXB * 3];
__device__ int   g_offs[MAXB + 1];
__device__ int   g_bcount;            // zero-init; self-resets each run

// Resolve lengths dtype (int32 vs int64) and build prefix offsets, per-thread.
__device__ __forceinline__ void resolve_offs(const void* __restrict__ lraw,
                                             int n, int b, int* offs, float* len)
{
    const long long* l64 = (const long long*)lraw;
    const int*       l32 = (const int*)lraw;
    long long s64 = 0;
    for (int i = 0; i < b; i++) s64 += l64[i];
    bool is64 = (s64 == (long long)n);
    int o = 0;
    offs[0] = 0;
    for (int i = 0; i < MAXB; i++) {
        long long L = (i < b) ? (is64 ? l64[i] : (long long)l32[i]) : 0;
        o += (int)L;
        offs[i + 1] = (i < b) ? o : n;
        if (len) len[i] = (float)((L < 1) ? 1 : L);
    }
}

// ---------------------------------------------------------------------------
// Kernel 1: partial sums per scene + last-block finalize (means & offsets).
// Warp-shuffle reductions; deterministic (fixed-order sums everywhere).
// ---------------------------------------------------------------------------
__global__ __launch_bounds__(256) void k_partial(
    const float* __restrict__ coord, const void* __restrict__ lraw, int n, int b)
{
    int offs[MAXB + 1];
    resolve_offs(lraw, n, b, offs, nullptr);

    float acc[MAXB][3];
#pragma unroll
    for (int s = 0; s < MAXB; s++) { acc[s][0] = 0.f; acc[s][1] = 0.f; acc[s][2] = 0.f; }

    int ngrp = (n + 3) >> 2;                       // groups of 4 rows
    int grp_per_block = (ngrp + gridDim.x - 1) / gridDim.x;
    int g0 = blockIdx.x * grp_per_block;
    int g1 = min(g0 + grp_per_block, ngrp);

    const float4* c4 = (const float4*)coord;
    for (int g = g0 + (int)threadIdx.x; g < g1; g += blockDim.x) {
        int r = g << 2;
        float v[12];
        if (r + 4 <= n) {
            float4 a = c4[3 * g + 0];
            float4 bq = c4[3 * g + 1];
            float4 c = c4[3 * g + 2];
            v[0]=a.x; v[1]=a.y; v[2]=a.z; v[3]=a.w;
            v[4]=bq.x; v[5]=bq.y; v[6]=bq.z; v[7]=bq.w;
            v[8]=c.x; v[9]=c.y; v[10]=c.z; v[11]=c.w;
        } else {
#pragma unroll
            for (int j = 0; j < 12; j++)
                v[j] = (r * 3 + j < n * 3) ? coord[r * 3 + j] : 0.f;
        }
#pragma unroll
        for (int k = 0; k < 4; k++) {
            int rr = r + k;
            if (rr < n) {
                int seg = 0;
#pragma unroll
                for (int s = 1; s < MAXB; s++) if (s < b && rr >= offs[s]) seg = s;
                acc[seg][0] += v[3 * k + 0];
                acc[seg][1] += v[3 * k + 1];
                acc[seg][2] += v[3 * k + 2];
            }
        }
    }

    // Warp-level butterfly reduction of all 24 components.
#pragma unroll
    for (int s = 0; s < MAXB; s++) {
#pragma unroll
        for (int d = 0; d < 3; d++) {
            float x = acc[s][d];
#pragma unroll
            for (int o = 16; o > 0; o >>= 1)
                x += __shfl_xor_sync(0xffffffffu, x, o);
            acc[s][d] = x;
        }
    }

    __shared__ float sm[8][MAXB * 3];      // 8 warps
    int wid = threadIdx.x >> 5, lane = threadIdx.x & 31;
    if (lane == 0) {
#pragma unroll
        for (int s = 0; s < MAXB; s++) {
            sm[wid][s * 3 + 0] = acc[s][0];
            sm[wid][s * 3 + 1] = acc[s][1];
            sm[wid][s * 3 + 2] = acc[s][2];
        }
    }
    __syncthreads();
    if (threadIdx.x < MAXB * 3) {
        float s_ = 0.f;
#pragma unroll
        for (int w = 0; w < 8; w++) s_ += sm[w][threadIdx.x];
        g_part[blockIdx.x][threadIdx.x] = s_;
    }

    // ---- last block finalizes ----
    __shared__ int s_last;
    __threadfence();
    if (threadIdx.x == 0) {
        int c = atomicAdd(&g_bcount, 1);
        s_last = (c == (int)gridDim.x - 1) ? 1 : 0;
    }
    __syncthreads();
    if (!s_last) return;

    int k = threadIdx.x;
    if (k < b * 3) {
        float s_ = 0.f;
        for (int p = 0; p < NPART; p++) s_ += g_part[p][k];
        float len[MAXB]; int o_[MAXB + 1];
        resolve_offs(lraw, n, b, o_, len);
        g_mean[k] = s_ / len[k / 3];
    }
    if (k >= 32 && k < 32 + MAXB + 1) {
        int o_[MAXB + 1];
        resolve_offs(lraw, n, b, o_, nullptr);
        g_offs[k - 32] = o_[k - 32];
    }
    __syncthreads();
    if (threadIdx.x == 0) g_bcount = 0;    // reset for next graph replay
}

// ---------------------------------------------------------------------------
// Fast GELU: exact formula with A&S 7.1.26 erf (|abs err| <= 1.5e-7).
// ---------------------------------------------------------------------------
__device__ __forceinline__ float gelu_fast(float x)
{
    float u = x * 0.70710678118654752f;
    float s = fabsf(u);
    float t = __fdividef(1.0f, fmaf(0.3275911f, s, 1.0f));
    float p = t * fmaf(t, fmaf(t, fmaf(t, fmaf(t, 1.061405429f, -1.453152027f),
                       1.421413741f), -0.284496736f), 0.254829592f);
    float e  = __expf(-u * u);
    float er = fmaf(-p, e, 1.0f);          // erf(|u|)
    er = copysignf(er, u);
    return 0.5f * x * (1.0f + er);
}

// ---------------------------------------------------------------------------
// Kernel 2: fused main kernel (R10 structure: per-row, params in smem).
// ---------------------------------------------------------------------------
#define LD8(dst, p) { float4 _u = s_par[p][lane]; float4 _v = s_par[p][32 + lane]; \
    dst[0]=_u.x; dst[1]=_u.y; dst[2]=_u.z; dst[3]=_u.w; \
    dst[4]=_v.x; dst[5]=_v.y; dst[6]=_v.z; dst[7]=_v.w; }

__global__ __launch_bounds__(128, 4) void k_main(
    const float* __restrict__ feat, const float* __restrict__ coord,
    const float* __restrict__ w_xyz, const float* __restrict__ b_xyz,
    const float* __restrict__ g1, const float* __restrict__ be1,
    const float* __restrict__ w_conv, const float* __restrict__ b_conv,
    const float* __restrict__ g2, const float* __restrict__ be2,
    float* __restrict__ out, int n, int b)
{
    __shared__ float4 s_par[12][64];     // 12 param arrays x 256 ch
    __shared__ int    s_offs[MAXB + 1];
    __shared__ float  s_mean[MAXB * 3];

    const int tid = threadIdx.x;
    for (int c = tid; c < CCH; c += 128) {
        ((float*)s_par[0])[c]  = w_xyz[c];
        ((float*)s_par[1])[c]  = w_xyz[CCH + c];
        ((float*)s_par[2])[c]  = w_xyz[2 * CCH + c];
        ((float*)s_par[3])[c]  = b_xyz[c];
        ((float*)s_par[4])[c]  = g1[c];
        ((float*)s_par[5])[c]  = be1[c];
        ((float*)s_par[6])[c]  = w_conv[3 * c + 0];
        ((float*)s_par[7])[c]  = w_conv[3 * c + 1];
        ((float*)s_par[8])[c]  = w_conv[3 * c + 2];
        ((float*)s_par[9])[c]  = b_conv[c];
        ((float*)s_par[10])[c] = g2[c];
        ((float*)s_par[11])[c] = be2[c];
    }
    if (tid <= MAXB)    s_offs[tid] = g_offs[tid];
    if (tid < MAXB * 3) s_mean[tid] = g_mean[tid];
    __syncthreads();

    const int lane  = tid & 31;
    const int gwarp = blockIdx.x * 4 + (tid >> 5);
    const int start = gwarp * WR;
    if (start >= n) return;
    const int end = min(start + WR, n);

    // Incremental segment state (rows visited in increasing order).
    int seg = 0;
    {
        int r0 = (start > 0) ? start - 1 : 0;
        while (seg < b - 1 && r0 >= s_offs[seg + 1]) seg++;
    }
    int bnd = s_offs[seg + 1];
    float mx = s_mean[seg * 3 + 0];
    float my = s_mean[seg * 3 + 1];
    float mz = s_mean[seg * 3 + 2];

    const float inv = 1.0f / (float)CCH;

    // f = feat + gelu(LN1(xyz_c @ W)); also returns raw feat row and seg id.
    auto compute_f = [&](int r, float* f, float* ft) -> int {
        while (r >= bnd) {
            seg++;
            bnd = s_offs[seg + 1];
            mx = s_mean[seg * 3 + 0];
            my = s_mean[seg * 3 + 1];
            mz = s_mean[seg * 3 + 2];
        }
        float cx = coord[3 * r + 0] - mx;
        float cy = coord[3 * r + 1] - my;
        float cz = coord[3 * r + 2] - mz;

        float wa[8], wb[8], wc_[8], wd[8];
        LD8(wa, 0); LD8(wb, 1); LD8(wc_, 2); LD8(wd, 3);

        float x[8];
        float s1 = 0.f, s2 = 0.f;
#pragma unroll
        for (int j = 0; j < 8; j++) {
            float v = fmaf(cx, wa[j], fmaf(cy, wb[j], fmaf(cz, wc_[j], wd[j])));
            x[j] = v;
            s1 += v;
            s2 = fmaf(v, v, s2);
        }
#pragma unroll
        for (int o = 16; o > 0; o >>= 1) {
            s1 += __shfl_xor_sync(0xffffffffu, s1, o);
            s2 += __shfl_xor_sync(0xffffffffu, s2, o);
        }
        float mu   = s1 * inv;
        float var  = fmaf(-mu, mu, s2 * inv);
        float rstd = rsqrtf(var + 1e-5f);

        const float4* fp4 = (const float4*)(feat + (long)r * CCH);
        float4 a = fp4[lane];
        float4 q = fp4[32 + lane];
        ft[0] = a.x; ft[1] = a.y; ft[2] = a.z; ft[3] = a.w;
        ft[4] = q.x; ft[5] = q.y; ft[6] = q.z; ft[7] = q.w;

        LD8(wa, 4); LD8(wb, 5);    // g1, be1
#pragma unroll
        for (int j = 0; j < 8; j++) {
            float t  = (x[j] - mu) * rstd;
            float ln = fmaf(t, wa[j], wb[j]);
            f[j] = ft[j] + gelu_fast(ln);
        }
        return seg;
    };

    float fprev[8], fcur[8], fnext[8], ftc[8], ftn[8];
    int segp, segc, segn;

    if (start > 0) {
        float dummy[8];
        segp = compute_f(start - 1, fprev, dummy);
    } else {
#pragma unroll
        for (int j = 0; j < 8; j++) fprev[j] = 0.f;
        segp = -1;
    }
    segc = compute_f(start, fcur, ftc);

    for (int r = start; r < end; r++) {
        if (r + 1 < n) {
            segn = compute_f(r + 1, fnext, ftn);
        } else {
#pragma unroll
            for (int j = 0; j < 8; j++) { fnext[j] = 0.f; ftn[j] = 0.f; }
            segn = -2;
        }

        float mp = (segp == segc) ? 1.f : 0.f;
        float mn = (segn == segc) ? 1.f : 0.f;

        float wa[8], wb[8], wc_[8], wd[8];
        LD8(wa, 6); LD8(wb, 7); LD8(wc_, 8); LD8(wd, 9);

        float y[8];
        float s1 = 0.f, s2 = 0.f;
#pragma unroll
        for (int j = 0; j < 8; j++) {
            float cv = fmaf(fprev[j] * mp, wa[j],
                       fmaf(fcur[j], wb[j],
                       fmaf(fnext[j] * mn, wc_[j], wd[j])));
            float v = ftc[j] + cv;
            y[j] = v;
            s1 += v;
            s2 = fmaf(v, v, s2);
        }
#pragma unroll
        for (int o = 16; o > 0; o >>= 1) {
            s1 += __shfl_xor_sync(0xffffffffu, s1, o);
            s2 += __shfl_xor_sync(0xffffffffu, s2, o);
        }
        float mu   = s1 * inv;
        float var  = fmaf(-mu, mu, s2 * inv);
        float rstd = rsqrtf(var + 1e-5f);

        LD8(wa, 10); LD8(wb, 11);  // g2, be2
        float4 o1, o2;
        o1.x = fmaf((y[0] - mu) * rstd, wa[0], wb[0]);
        o1.y = fmaf((y[1] - mu) * rstd, wa[1], wb[1]);
        o1.z = fmaf((y[2] - mu) * rstd, wa[2], wb[2]);
        o1.w = fmaf((y[3] - mu) * rstd, wa[3], wb[3]);
        o2.x = fmaf((y[4] - mu) * rstd, wa[4], wb[4]);
        o2.y = fmaf((y[5] - mu) * rstd, wa[5], wb[5]);
        o2.z = fmaf((y[6] - mu) * rstd, wa[6], wb[6]);
        o2.w = fmaf((y[7] - mu) * rstd, wa[7], wb[7]);

        float4* op4 = (float4*)(out + (long)r * CCH);
        op4[lane]      = o1;
        op4[32 + lane] = o2;

        // rotate window
        segp = segc; segc = segn;
#pragma unroll
        for (int j = 0; j < 8; j++) {
            fprev[j] = fcur[j];
            fcur[j]  = fnext[j];
            ftc[j]   = ftn[j];
        }
    }
}

// ---------------------------------------------------------------------------
extern "C" void kernel_launch(void* const* d_in, const int* in_sizes, int n_in,
                              void* d_out, int out_size)
{
    const float* feat    = (const float*)d_in[0];
    const float* coord   = (const float*)d_in[1];
    const void*  lengths = (const void*)d_in[2];
    const float* w_xyz   = (const float*)d_in[3];
    const float* b_xyz   = (const float*)d_in[4];
    const float* g1      = (const float*)d_in[5];
    const float* be1     = (const float*)d_in[6];
    const float* w_conv  = (const float*)d_in[7];
    const float* b_conv  = (const float*)d_in[8];
    const float* g2      = (const float*)d_in[9];
    const float* be2     = (const float*)d_in[10];
    float*       out     = (float*)d_out;

    int n = in_sizes[0] / CCH;
    int b = in_sizes[2];
    if (b > MAXB) b = MAXB;

    k_partial<<<NPART, 256>>>(coord, lengths, n, b);

    int warps  = (n + WR - 1) / WR;
    int blocks = (warps + 3) / 4;
    k_main<<<blocks, 128>>>(feat, coord, w_xyz, b_xyz, g1, be1,
                            w_conv, b_conv, g2, be2, out, n, b);
}

// round 15
// speedup vs baseline: 1.0791x; 1.0300x over previous
#include <cuda_runtime.h>
#include <math.h>

// Problem constants (fixed by the dataset): C=256 channels.
#define CCH   256
#define WR    64      // rows per warp
#define MAXB  8       // scenes
#define NPART 256     // partial-sum blocks for scene means

typedef unsigned long long u64;

__device__ float g_part[NPART][MAXB * 3];
__device__ float g_mean[MAXB * 3];
__device__ int   g_offs[MAXB + 1];
__device__ int   g_bcount;            // zero-init; self-resets each run

// ---- packed f32x2 helpers (sm_103a SIMD2 fp32; ptxas never auto-fuses) ----
__device__ __forceinline__ u64 pk2(float lo, float hi) {
    u64 r; asm("mov.b64 %0, {%1, %2};" : "=l"(r) : "f"(lo), "f"(hi)); return r;
}
__device__ __forceinline__ void upk2(u64 v, float& lo, float& hi) {
    asm("mov.b64 {%0, %1}, %2;" : "=f"(lo), "=f"(hi) : "l"(v));
}
__device__ __forceinline__ u64 fma2_(u64 a, u64 b, u64 c) {
    u64 r; asm("fma.rn.f32x2 %0, %1, %2, %3;" : "=l"(r) : "l"(a), "l"(b), "l"(c)); return r;
}
__device__ __forceinline__ u64 add2_(u64 a, u64 b) {
    u64 r; asm("add.rn.f32x2 %0, %1, %2;" : "=l"(r) : "l"(a), "l"(b)); return r;
}
__device__ __forceinline__ u64 mul2_(u64 a, u64 b) {
    u64 r; asm("mul.rn.f32x2 %0, %1, %2;" : "=l"(r) : "l"(a), "l"(b)); return r;
}

// Resolve lengths dtype (int32 vs int64) and build prefix offsets, per-thread.
__device__ __forceinline__ void resolve_offs(const void* __restrict__ lraw,
                                             int n, int b, int* offs, float* len)
{
    const long long* l64 = (const long long*)lraw;
    const int*       l32 = (const int*)lraw;
    long long s64 = 0;
    for (int i = 0; i < b; i++) s64 += l64[i];
    bool is64 = (s64 == (long long)n);
    int o = 0;
    offs[0] = 0;
    for (int i = 0; i < MAXB; i++) {
        long long L = (i < b) ? (is64 ? l64[i] : (long long)l32[i]) : 0;
        o += (int)L;
        offs[i + 1] = (i < b) ? o : n;
        if (len) len[i] = (float)((L < 1) ? 1 : L);
    }
}

// ---------------------------------------------------------------------------
// Kernel 1: partial sums per scene + last-block finalize (means & offsets).
// ---------------------------------------------------------------------------
__global__ __launch_bounds__(256) void k_partial(
    const float* __restrict__ coord, const void* __restrict__ lraw, int n, int b)
{
    int offs[MAXB + 1];
    resolve_offs(lraw, n, b, offs, nullptr);

    float acc[MAXB][3];
#pragma unroll
    for (int s = 0; s < MAXB; s++) { acc[s][0] = 0.f; acc[s][1] = 0.f; acc[s][2] = 0.f; }

    int ngrp = (n + 3) >> 2;                       // groups of 4 rows
    int grp_per_block = (ngrp + gridDim.x - 1) / gridDim.x;
    int g0 = blockIdx.x * grp_per_block;
    int g1 = min(g0 + grp_per_block, ngrp);

    const float4* c4 = (const float4*)coord;
    for (int g = g0 + (int)threadIdx.x; g < g1; g += blockDim.x) {
        int r = g << 2;
        float v[12];
        if (r + 4 <= n) {
            float4 a = c4[3 * g + 0];
            float4 bq = c4[3 * g + 1];
            float4 c = c4[3 * g + 2];
            v[0]=a.x; v[1]=a.y; v[2]=a.z; v[3]=a.w;
            v[4]=bq.x; v[5]=bq.y; v[6]=bq.z; v[7]=bq.w;
            v[8]=c.x; v[9]=c.y; v[10]=c.z; v[11]=c.w;
        } else {
#pragma unroll
            for (int j = 0; j < 12; j++)
                v[j] = (r * 3 + j < n * 3) ? coord[r * 3 + j] : 0.f;
        }
#pragma unroll
        for (int k = 0; k < 4; k++) {
            int rr = r + k;
            if (rr < n) {
                int seg = 0;
#pragma unroll
                for (int s = 1; s < MAXB; s++) if (s < b && rr >= offs[s]) seg = s;
                acc[seg][0] += v[3 * k + 0];
                acc[seg][1] += v[3 * k + 1];
                acc[seg][2] += v[3 * k + 2];
            }
        }
    }

#pragma unroll
    for (int s = 0; s < MAXB; s++) {
#pragma unroll
        for (int d = 0; d < 3; d++) {
            float x = acc[s][d];
#pragma unroll
            for (int o = 16; o > 0; o >>= 1)
                x += __shfl_xor_sync(0xffffffffu, x, o);
            acc[s][d] = x;
        }
    }

    __shared__ float sm[8][MAXB * 3];      // 8 warps
    int wid = threadIdx.x >> 5, lane = threadIdx.x & 31;
    if (lane == 0) {
#pragma unroll
        for (int s = 0; s < MAXB; s++) {
            sm[wid][s * 3 + 0] = acc[s][0];
            sm[wid][s * 3 + 1] = acc[s][1];
            sm[wid][s * 3 + 2] = acc[s][2];
        }
    }
    __syncthreads();
    if (threadIdx.x < MAXB * 3) {
        float s_ = 0.f;
#pragma unroll
        for (int w = 0; w < 8; w++) s_ += sm[w][threadIdx.x];
        g_part[blockIdx.x][threadIdx.x] = s_;
    }

    // ---- last block finalizes ----
    __shared__ int s_last;
    __threadfence();
    if (threadIdx.x == 0) {
        int c = atomicAdd(&g_bcount, 1);
        s_last = (c == (int)gridDim.x - 1) ? 1 : 0;
    }
    __syncthreads();
    if (!s_last) return;

    int k = threadIdx.x;
    if (k < b * 3) {
        float s_ = 0.f;
        for (int p = 0; p < NPART; p++) s_ += g_part[p][k];
        float len[MAXB]; int o_[MAXB + 1];
        resolve_offs(lraw, n, b, o_, len);
        g_mean[k] = s_ / len[k / 3];
    }
    if (k >= 32 && k < 32 + MAXB + 1) {
        int o_[MAXB + 1];
        resolve_offs(lraw, n, b, o_, nullptr);
        g_offs[k - 32] = o_[k - 32];
    }
    __syncthreads();
    if (threadIdx.x == 0) g_bcount = 0;    // reset for next graph replay
}

// ---------------------------------------------------------------------------
// Fast GELU: exact formula with A&S 7.1.26 erf (|abs err| <= 1.5e-7).
// ---------------------------------------------------------------------------
__device__ __forceinline__ float gelu_fast(float x)
{
    float u = x * 0.70710678118654752f;
    float s = fabsf(u);
    float t = __fdividef(1.0f, fmaf(0.3275911f, s, 1.0f));
    float p = t * fmaf(t, fmaf(t, fmaf(t, fmaf(t, 1.061405429f, -1.453152027f),
                       1.421413741f), -0.284496736f), 0.254829592f);
    float e  = __expf(-u * u);
    float er = fmaf(-p, e, 1.0f);          // erf(|u|)
    er = copysignf(er, u);
    return 0.5f * x * (1.0f + er);
}

// ---------------------------------------------------------------------------
// Kernel 2: fused main kernel — packed f32x2 datapath.
// Lane owns 8 channels as 4 f32x2 pairs; params in smem read as ulonglong2.
// ---------------------------------------------------------------------------
#define LDP(dst, p) { ulonglong2 _u = *(const ulonglong2*)&s_par[p][lane]; \
                      ulonglong2 _v = *(const ulonglong2*)&s_par[p][32 + lane]; \
                      dst[0]=_u.x; dst[1]=_u.y; dst[2]=_v.x; dst[3]=_v.y; }

__global__ __launch_bounds__(128, 4) void k_main(
    const float* __restrict__ feat, const float* __restrict__ coord,
    const float* __restrict__ w_xyz, const float* __restrict__ b_xyz,
    const float* __restrict__ g1, const float* __restrict__ be1,
    const float* __restrict__ w_conv, const float* __restrict__ b_conv,
    const float* __restrict__ g2, const float* __restrict__ be2,
    float* __restrict__ out, int n, int b)
{
    __shared__ float4 s_par[12][64];     // 12 param arrays x 256 ch
    __shared__ int    s_offs[MAXB + 1];
    __shared__ float  s_mean[MAXB * 3];

    const int tid = threadIdx.x;
    for (int c = tid; c < CCH; c += 128) {
        ((float*)s_par[0])[c]  = w_xyz[c];
        ((float*)s_par[1])[c]  = w_xyz[CCH + c];
        ((float*)s_par[2])[c]  = w_xyz[2 * CCH + c];
        ((float*)s_par[3])[c]  = b_xyz[c];
        ((float*)s_par[4])[c]  = g1[c];
        ((float*)s_par[5])[c]  = be1[c];
        ((float*)s_par[6])[c]  = w_conv[3 * c + 0];
        ((float*)s_par[7])[c]  = w_conv[3 * c + 1];
        ((float*)s_par[8])[c]  = w_conv[3 * c + 2];
        ((float*)s_par[9])[c]  = b_conv[c];
        ((float*)s_par[10])[c] = g2[c];
        ((float*)s_par[11])[c] = be2[c];
    }
    if (tid <= MAXB)    s_offs[tid] = g_offs[tid];
    if (tid < MAXB * 3) s_mean[tid] = g_mean[tid];
    __syncthreads();

    const int lane  = tid & 31;
    const int gwarp = blockIdx.x * 4 + (tid >> 5);
    const int start = gwarp * WR;
    if (start >= n) return;
    const int end = min(start + WR, n);

    // Incremental segment state.
    int seg = 0;
    {
        int r0 = (start > 0) ? start - 1 : 0;
        while (seg < b - 1 && r0 >= s_offs[seg + 1]) seg++;
    }
    int bnd = s_offs[seg + 1];
    float mx = s_mean[seg * 3 + 0];
    float my = s_mean[seg * 3 + 1];
    float mz = s_mean[seg * 3 + 2];

    const float inv = 1.0f / (float)CCH;

    // f = feat + gelu(LN1(xyz_c @ W)) — packed pairs. Returns seg id.
    auto compute_f = [&](int r, u64* f, u64* ft) -> int {
        while (r >= bnd) {
            seg++;
            bnd = s_offs[seg + 1];
            mx = s_mean[seg * 3 + 0];
            my = s_mean[seg * 3 + 1];
            mz = s_mean[seg * 3 + 2];
        }
        float cx = coord[3 * r + 0] - mx;
        float cy = coord[3 * r + 1] - my;
        float cz = coord[3 * r + 2] - mz;
        u64 cx2 = pk2(cx, cx), cy2 = pk2(cy, cy), cz2 = pk2(cz, cz);

        u64 wa[4], wb[4], wc_[4], wd[4];
        LDP(wa, 0); LDP(wb, 1); LDP(wc_, 2); LDP(wd, 3);

        u64 x[4];
        u64 s1v = 0ull, s2v = 0ull;
#pragma unroll
        for (int j = 0; j < 4; j++) {
            u64 v = fma2_(cx2, wa[j], fma2_(cy2, wb[j], fma2_(cz2, wc_[j], wd[j])));
            x[j] = v;
            s1v = add2_(s1v, v);
            s2v = fma2_(v, v, s2v);
        }
        float s1, s2;
        {
            float a0, a1, b0, b1;
            upk2(s1v, a0, a1); s1 = a0 + a1;
            upk2(s2v, b0, b1); s2 = b0 + b1;
        }
#pragma unroll
        for (int o = 16; o > 0; o >>= 1) {
            s1 += __shfl_xor_sync(0xffffffffu, s1, o);
            s2 += __shfl_xor_sync(0xffffffffu, s2, o);
        }
        float mu   = s1 * inv;
        float var  = fmaf(-mu, mu, s2 * inv);
        float rstd = rsqrtf(var + 1e-5f);
        float sb   = -mu * rstd;
        u64 a2 = pk2(rstd, rstd), b2 = pk2(sb, sb);

        const ulonglong2* fp8 = (const ulonglong2*)(feat + (long)r * CCH);
        ulonglong2 fa = fp8[lane];
        ulonglong2 fq = fp8[32 + lane];
        ft[0] = fa.x; ft[1] = fa.y; ft[2] = fq.x; ft[3] = fq.y;

        LDP(wa, 4); LDP(wb, 5);    // g1, be1
#pragma unroll
        for (int j = 0; j < 4; j++) {
            u64 t2  = fma2_(x[j], a2, b2);
            u64 ln2 = fma2_(t2, wa[j], wb[j]);
            float l0, l1;
            upk2(ln2, l0, l1);
            f[j] = add2_(ft[j], pk2(gelu_fast(l0), gelu_fast(l1)));
        }
        return seg;
    };

    u64 fprev[4], fcur[4], fnext[4], ftc[4], ftn[4];
    int segp, segc, segn;

    if (start > 0) {
        u64 dummy[4];
        segp = compute_f(start - 1, fprev, dummy);
    } else {
#pragma unroll
        for (int j = 0; j < 4; j++) fprev[j] = 0ull;
        segp = -1;
    }
    segc = compute_f(start, fcur, ftc);

    for (int r = start; r < end; r++) {
        if (r + 1 < n) {
            segn = compute_f(r + 1, fnext, ftn);
        } else {
#pragma unroll
            for (int j = 0; j < 4; j++) { fnext[j] = 0ull; ftn[j] = 0ull; }
            segn = -2;
        }

        float mp = (segp == segc) ? 1.f : 0.f;
        float mn = (segn == segc) ? 1.f : 0.f;
        u64 mp2 = pk2(mp, mp), mn2 = pk2(mn, mn);

        u64 wa[4], wb[4], wc_[4], wd[4];
        LDP(wa, 6); LDP(wb, 7); LDP(wc_, 8); LDP(wd, 9);

        u64 y[4];
        u64 s1v = 0ull, s2v = 0ull;
#pragma unroll
        for (int j = 0; j < 4; j++) {
            u64 cv = fma2_(mul2_(fprev[j], mp2), wa[j],
                     fma2_(fcur[j], wb[j],
                     fma2_(mul2_(fnext[j], mn2), wc_[j], wd[j])));
            u64 v = add2_(ftc[j], cv);
            y[j] = v;
            s1v = add2_(s1v, v);
            s2v = fma2_(v, v, s2v);
        }
        float s1, s2;
        {
            float a0, a1, b0, b1;
            upk2(s1v, a0, a1); s1 = a0 + a1;
            upk2(s2v, b0, b1); s2 = b0 + b1;
        }
#pragma unroll
        for (int o = 16; o > 0; o >>= 1) {
            s1 += __shfl_xor_sync(0xffffffffu, s1, o);
            s2 += __shfl_xor_sync(0xffffffffu, s2, o);
        }
        float mu   = s1 * inv;
        float var  = fmaf(-mu, mu, s2 * inv);
        float rstd = rsqrtf(var + 1e-5f);
        float sb   = -mu * rstd;
        u64 a2 = pk2(rstd, rstd), b2 = pk2(sb, sb);

        LDP(wa, 10); LDP(wb, 11);  // g2, be2
        ulonglong2 st0, st1;
        st0.x = fma2_(fma2_(y[0], a2, b2), wa[0], wb[0]);
        st0.y = fma2_(fma2_(y[1], a2, b2), wa[1], wb[1]);
        st1.x = fma2_(fma2_(y[2], a2, b2), wa[2], wb[2]);
        st1.y = fma2_(fma2_(y[3], a2, b2), wa[3], wb[3]);

        ulonglong2* op8 = (ulonglong2*)(out + (long)r * CCH);
        op8[lane]      = st0;
        op8[32 + lane] = st1;

        // rotate window
        segp = segc; segc = segn;
#pragma unroll
        for (int j = 0; j < 4; j++) {
            fprev[j] = fcur[j];
            fcur[j]  = fnext[j];
            ftc[j]   = ftn[j];
        }
    }
}

// ---------------------------------------------------------------------------
extern "C" void kernel_launch(void* const* d_in, const int* in_sizes, int n_in,
                              void* d_out, int out_size)
{
    const float* feat    = (const float*)d_in[0];
    const float* coord   = (const float*)d_in[1];
    const void*  lengths = (const void*)d_in[2];
    const float* w_xyz   = (const float*)d_in[3];
    const float* b_xyz   = (const float*)d_in[4];
    const float* g1      = (const float*)d_in[5];
    const float* be1     = (const float*)d_in[6];
    const float* w_conv  = (const float*)d_in[7];
    const float* b_conv  = (const float*)d_in[8];
    const float* g2      = (const float*)d_in[9];
    const float* be2     = (const float*)d_in[10];
    float*       out     = (float*)d_out;

    int n = in_sizes[0] / CCH;
    int b = in_sizes[2];
    if (b > MAXB) b = MAXB;

    k_partial<<<NPART, 256>>>(coord, lengths, n, b);

    int warps  = (n + WR - 1) / WR;
    int blocks = (warps + 3) / 4;
    k_main<<<blocks, 128>>>(feat, coord, w_xyz, b_xyz, g1, be1,
                            w_conv, b_conv, g2, be2, out, n, b);
}